// round 12
// baseline (speedup 1.0000x reference)
#include <cuda_runtime.h>
#include <cuda_bf16.h>
#include <cuda_fp16.h>
#include <cstdint>

// ---------------- Problem constants ----------------
#define EMBED   256
#define HEADS   8
#define LEVELS  4
#define POINTS  4
#define CDIM    32
#define LEN_V   5440
#define LEN_Q   5440
#define BSZ     4
#define MROWS   (BSZ * LEN_Q)   // 21760

// ---------------- Scratch ----------------
__device__ __half g_vh  [(size_t)MROWS * EMBED];  // projected value, fp16
__device__ float  g_off [(size_t)MROWS * EMBED];
__device__ float  g_awl [(size_t)MROWS * 128];
__device__ __half g_samp[(size_t)MROWS * EMBED];  // sampler output, fp16

// fp16 transposed weights [N,K]: vproj:0, off:65536, attn:131072, out:163840
__device__ __half g_wh[229376];

// ---------------- PTX helpers (generic ISA only) ----------------
__device__ __forceinline__ uint32_t smem_u32(const void* p) {
    uint32_t a;
    asm("{ .reg .u64 t; cvta.to.shared.u64 t, %1; cvt.u32.u64 %0, t; }" : "=r"(a) : "l"(p));
    return a;
}
__device__ __forceinline__ void ldm_x4(uint32_t* r, uint32_t addr) {
    asm volatile("ldmatrix.sync.aligned.m8n8.x4.shared.b16 {%0,%1,%2,%3}, [%4];"
        : "=r"(r[0]), "=r"(r[1]), "=r"(r[2]), "=r"(r[3]) : "r"(addr));
}
__device__ __forceinline__ void mma_f16(float* c, const uint32_t* a, const uint32_t* b) {
    asm volatile(
        "mma.sync.aligned.m16n8k16.row.col.f32.f16.f16.f32 "
        "{%0,%1,%2,%3}, {%4,%5,%6,%7}, {%8,%9}, {%0,%1,%2,%3};"
        : "+f"(c[0]), "+f"(c[1]), "+f"(c[2]), "+f"(c[3])
        : "r"(a[0]), "r"(a[1]), "r"(a[2]), "r"(a[3]), "r"(b[0]), "r"(b[1]));
}
__device__ __forceinline__ void cp16(uint32_t dst, const void* src) {
    asm volatile("cp.async.cg.shared.global [%0], [%1], 16;" :: "r"(dst), "l"(src));
}
#define CP_COMMIT() asm volatile("cp.async.commit_group;" ::: "memory")
#define CP_WAIT0()  asm volatile("cp.async.wait_group 0;" ::: "memory")

__device__ __forceinline__ uint32_t pk_h2(float x, float y) {
    const __half2 h = __floats2half2_rn(x, y);
    return *(const uint32_t*)&h;
}

// swizzled smem offset (16-bit elements): row stride 64, 16B chunk xor (row&7)
__device__ __forceinline__ int swz(int row, int k) {
    return row * 64 + ((((k >> 3) ^ row) & 7) << 3) + (k & 7);
}

#define STAGE_B 24576      // A 16KB @0, B 8KB @16384

// ====================== merged projection GEMM ==============================
// grid (MROWS/128, 10). y<4: A=value(f32) -> g_vh fp16, W vproj.
// y in [4,8): A=query -> g_off fp32. y in [8,10): A=query -> g_awl fp32.
// A converted fp32->fp16 in-register during staging; B weights via cp.async.
// 2-stage smem pipeline (48 KB).
#define PROJ_SMEM (2 * STAGE_B)

__global__ __launch_bounds__(256)
void gemm_proj(const float* __restrict__ A0, const float* __restrict__ A1,
               const __half* __restrict__ Wh,
               const float* __restrict__ bV, const float* __restrict__ bO,
               const float* __restrict__ bA)
{
    extern __shared__ char sm[];
    const uint32_t uS = smem_u32(sm);

    const int tid  = threadIdx.x;
    const int lane = tid & 31;
    const int wid  = tid >> 5;
    const int wm   = wid & 3;
    const int wn   = wid >> 2;
    const int bm   = blockIdx.x * 128;
    const int by   = blockIdx.y;

    const float*  pA = ((by < 4) ? A0 : A1) + (size_t)bm * EMBED;
    const __half* pB = (by < 4) ? (Wh + (size_t)by * 64 * 256)
                                : (Wh + 65536 + (size_t)(by - 4) * 64 * 256);

    const int grow = tid >> 3;   // 0..31
    const int gc8  = tid & 7;    // 8-half chunk

    float c[2][4][4];
    #pragma unroll
    for (int mt = 0; mt < 2; ++mt)
        #pragma unroll
        for (int nt = 0; nt < 4; ++nt)
            #pragma unroll
            for (int i = 0; i < 4; ++i) c[mt][nt][i] = 0.f;

    uint32_t aq[4][4];   // 4 rows x 8 halves (converted A for one chunk)

    auto ldgA = [&](int kc) {
        #pragma unroll
        for (int t = 0; t < 4; ++t) {
            const int row = grow + t * 32;
            const float* src = pA + (size_t)row * EMBED + kc * 64 + gc8 * 8;
            const float4 f0 = *(const float4*)(src);
            const float4 f1 = *(const float4*)(src + 4);
            aq[t][0] = pk_h2(f0.x, f0.y);
            aq[t][1] = pk_h2(f0.z, f0.w);
            aq[t][2] = pk_h2(f1.x, f1.y);
            aq[t][3] = pk_h2(f1.z, f1.w);
        }
    };
    auto stsA = [&](int s) {
        #pragma unroll
        for (int t = 0; t < 4; ++t) {
            const int row = grow + t * 32;
            *(uint4*)(sm + s * STAGE_B + swz(row, gc8 * 8) * 2) =
                make_uint4(aq[t][0], aq[t][1], aq[t][2], aq[t][3]);
        }
    };
    auto cpB = [&](int kc, int s) {
        const uint32_t sb = uS + s * STAGE_B + 16384;
        #pragma unroll
        for (int t = 0; t < 2; ++t) {
            const int row = grow + t * 32;
            cp16(sb + (uint32_t)swz(row, gc8 * 8) * 2,
                 pB + (size_t)row * EMBED + kc * 64 + gc8 * 8);
        }
        CP_COMMIT();
    };

    const int a_r = (lane & 15);
    const int a_k = (lane >> 4) << 3;
    const int b_n = ((lane >> 4) << 3) + (lane & 7);
    const int b_k = ((lane >> 3) & 1) << 3;

    auto compute = [&](int s) {
        const uint32_t uA = uS + s * STAGE_B;
        const uint32_t uB = uA + 16384;
        #pragma unroll
        for (int ks = 0; ks < 4; ++ks) {
            uint32_t a[2][4], b[4][2];
            #pragma unroll
            for (int mt = 0; mt < 2; ++mt)
                ldm_x4(a[mt], uA + swz(wm * 32 + mt * 16 + a_r, ks * 16 + a_k) * 2);
            #pragma unroll
            for (int np = 0; np < 2; ++np) {
                uint32_t t4[4];
                ldm_x4(t4, uB + swz(wn * 32 + np * 16 + b_n, ks * 16 + b_k) * 2);
                b[np * 2 + 0][0] = t4[0]; b[np * 2 + 0][1] = t4[1];
                b[np * 2 + 1][0] = t4[2]; b[np * 2 + 1][1] = t4[3];
            }
            #pragma unroll
            for (int mt = 0; mt < 2; ++mt)
                #pragma unroll
                for (int nt = 0; nt < 4; ++nt)
                    mma_f16(c[mt][nt], a[mt], b[nt]);
        }
    };

    // prologue
    ldgA(0);
    stsA(0); cpB(0, 0);
    ldgA(1);
    CP_WAIT0();
    __syncthreads();

    #pragma unroll
    for (int kc = 0; kc < 4; ++kc) {
        const int s = kc & 1;
        if (kc < 3) {
            stsA(s ^ 1);            // A for chunk kc+1 (already in regs)
            cpB(kc + 1, s ^ 1);
            if (kc < 2) ldgA(kc + 2);   // overlaps compute below
        }
        compute(s);
        if (kc < 3) CP_WAIT0();
        __syncthreads();
    }

    // ---- epilogue (3-way dispatch) ----
    if (by < 4) {
        const int colbase = by * 64;
        #pragma unroll
        for (int mt = 0; mt < 2; ++mt) {
            const int r0 = bm + wm * 32 + mt * 16 + (lane >> 2);
            #pragma unroll
            for (int nt = 0; nt < 4; ++nt) {
                const int col = colbase + wn * 32 + nt * 8 + (lane & 3) * 2;
                const float2 bv = *(const float2*)(bV + col);
                *(__half2*)(g_vh + (size_t)r0 * 256 + col) =
                    __floats2half2_rn(c[mt][nt][0] + bv.x, c[mt][nt][1] + bv.y);
                *(__half2*)(g_vh + (size_t)(r0 + 8) * 256 + col) =
                    __floats2half2_rn(c[mt][nt][2] + bv.x, c[mt][nt][3] + bv.y);
            }
        }
    } else {
        const bool isOff = (by < 8);
        float* Cf = isOff ? g_off : g_awl;
        const float* bs = isOff ? bO : bA;
        const int Nt = isOff ? 256 : 128;
        const int colbase = (isOff ? (by - 4) : (by - 8)) * 64;
        #pragma unroll
        for (int mt = 0; mt < 2; ++mt) {
            const int r0 = bm + wm * 32 + mt * 16 + (lane >> 2);
            #pragma unroll
            for (int nt = 0; nt < 4; ++nt) {
                const int col = colbase + wn * 32 + nt * 8 + (lane & 3) * 2;
                const float2 bv = *(const float2*)(bs + col);
                *(float2*)(Cf + (size_t)r0 * Nt + col) =
                    make_float2(c[mt][nt][0] + bv.x, c[mt][nt][1] + bv.y);
                *(float2*)(Cf + (size_t)(r0 + 8) * Nt + col) =
                    make_float2(c[mt][nt][2] + bv.x, c[mt][nt][3] + bv.y);
            }
        }
    }
}

// ====================== out-proj GEMM (fp16 A via cp.async, 3-stage) ========
#define OUT_SMEM (3 * STAGE_B)

__global__ __launch_bounds__(256)
void gemm_out(const __half* __restrict__ A, const __half* __restrict__ BT,
              const float* __restrict__ bias, float* __restrict__ C)
{
    extern __shared__ char sm[];
    const uint32_t uS = smem_u32(sm);

    const int tid  = threadIdx.x;
    const int lane = tid & 31;
    const int wid  = tid >> 5;
    const int wm   = wid & 3;
    const int wn   = wid >> 2;
    const int bm   = blockIdx.x * 128;
    const int bn   = blockIdx.y * 64;

    const __half* pA = A  + (size_t)bm * EMBED;
    const __half* pB = BT + (size_t)bn * EMBED;

    const int grow = tid >> 3;
    const int gc8  = tid & 7;

    float c[2][4][4];
    #pragma unroll
    for (int mt = 0; mt < 2; ++mt)
        #pragma unroll
        for (int nt = 0; nt < 4; ++nt)
            #pragma unroll
            for (int i = 0; i < 4; ++i) c[mt][nt][i] = 0.f;

    auto stage_load = [&](int kc, int s) {
        const uint32_t sb = uS + s * STAGE_B;
        #pragma unroll
        for (int t = 0; t < 4; ++t) {
            const int row = grow + t * 32;
            cp16(sb + (uint32_t)swz(row, gc8 * 8) * 2,
                 pA + (size_t)row * EMBED + kc * 64 + gc8 * 8);
        }
        #pragma unroll
        for (int t = 0; t < 2; ++t) {
            const int row = grow + t * 32;
            cp16(sb + 16384 + (uint32_t)swz(row, gc8 * 8) * 2,
                 pB + (size_t)row * EMBED + kc * 64 + gc8 * 8);
        }
        CP_COMMIT();
    };

    const int a_r = (lane & 15);
    const int a_k = (lane >> 4) << 3;
    const int b_n = ((lane >> 4) << 3) + (lane & 7);
    const int b_k = ((lane >> 3) & 1) << 3;

    stage_load(0, 0);
    stage_load(1, 1);
    #pragma unroll
    for (int kc = 0; kc < 4; ++kc) {
        const int s = kc % 3;
        if (kc < 2) {
            stage_load(kc + 2, (kc + 2) % 3);
            asm volatile("cp.async.wait_group 2;" ::: "memory");
        } else if (kc == 2) {
            asm volatile("cp.async.wait_group 1;" ::: "memory");
        } else {
            asm volatile("cp.async.wait_group 0;" ::: "memory");
        }
        __syncthreads();

        const uint32_t uA = uS + s * STAGE_B;
        const uint32_t uB = uA + 16384;

        #pragma unroll
        for (int ks = 0; ks < 4; ++ks) {
            uint32_t a[2][4], b[4][2];
            #pragma unroll
            for (int mt = 0; mt < 2; ++mt)
                ldm_x4(a[mt], uA + swz(wm * 32 + mt * 16 + a_r, ks * 16 + a_k) * 2);
            #pragma unroll
            for (int np = 0; np < 2; ++np) {
                uint32_t t4[4];
                ldm_x4(t4, uB + swz(wn * 32 + np * 16 + b_n, ks * 16 + b_k) * 2);
                b[np * 2 + 0][0] = t4[0]; b[np * 2 + 0][1] = t4[1];
                b[np * 2 + 1][0] = t4[2]; b[np * 2 + 1][1] = t4[3];
            }
            #pragma unroll
            for (int mt = 0; mt < 2; ++mt)
                #pragma unroll
                for (int nt = 0; nt < 4; ++nt)
                    mma_f16(c[mt][nt], a[mt], b[nt]);
        }
        __syncthreads();
    }

    #pragma unroll
    for (int mt = 0; mt < 2; ++mt) {
        const int r0 = bm + wm * 32 + mt * 16 + (lane >> 2);
        #pragma unroll
        for (int nt = 0; nt < 4; ++nt) {
            const int col = bn + wn * 32 + nt * 8 + (lane & 3) * 2;
            const float2 bv = *(const float2*)(bias + col);
            *(float2*)(C + (size_t)r0 * 256 + col) =
                make_float2(c[mt][nt][0] + bv.x, c[mt][nt][1] + bv.y);
            *(float2*)(C + (size_t)(r0 + 8) * 256 + col) =
                make_float2(c[mt][nt][2] + bv.x, c[mt][nt][3] + bv.y);
        }
    }
}

// ---------------- weight transpose: g_wh[off + n*256 + k] = W[k*N + n] ------
__global__ __launch_bounds__(256)
void conv_wt(const float* __restrict__ w0, const float* __restrict__ w1,
             const float* __restrict__ w2, const float* __restrict__ w3)
{
    const int m = blockIdx.y;
    const float* W = (m == 0) ? w0 : (m == 1) ? w1 : (m == 2) ? w2 : w3;
    const int N   = (m == 2) ? 128 : 256;
    const int off = (m == 0) ? 0 : (m == 1) ? 65536 : (m == 2) ? 131072 : 163840;
    const int idx = blockIdx.x * 256 + threadIdx.x;
    if (idx >= N * 256) return;
    const int k = idx & 255, n = idx >> 8;
    g_wh[off + idx] = __float2half(W[(size_t)k * N + n]);
}

// ---------------- Sampling kernel (fp16 v, fp16 samp output) ----------------
__global__ __launch_bounds__(256)
void msda_sample(const float* __restrict__ ref, __half* __restrict__ samp)
{
    const int bq   = blockIdx.x;
    const int b    = bq / LEN_Q;
    const int h    = threadIdx.x >> 5;
    const int lane = threadIdx.x & 31;
    const int p4   = lane >> 3;
    const int cg   = lane & 7;

    const float*  off = g_off + (size_t)bq * EMBED + h * 32;
    const float*  awl = g_awl + (size_t)bq * 128 + h * 16;
    const __half* vb  = g_vh + (size_t)b * LEN_V * EMBED + h * CDIM + cg * 4;
    const float*  rp  = ref + (size_t)bq * 8;

    float4 r01 = ((const float4*)rp)[0];
    float4 r23 = ((const float4*)rp)[1];
    const float rx[4] = {r01.x, r01.z, r23.x, r23.z};
    const float ry[4] = {r01.y, r01.w, r23.y, r23.w};

    float e[4];
    e[0] = awl[p4]; e[1] = awl[4 + p4]; e[2] = awl[8 + p4]; e[3] = awl[12 + p4];
    float mx = fmaxf(fmaxf(e[0], e[1]), fmaxf(e[2], e[3]));
    mx = fmaxf(mx, __shfl_xor_sync(0xffffffffu, mx, 8));
    mx = fmaxf(mx, __shfl_xor_sync(0xffffffffu, mx, 16));
    float s = 0.f;
    #pragma unroll
    for (int l = 0; l < 4; ++l) { e[l] = __expf(e[l] - mx); s += e[l]; }
    s += __shfl_xor_sync(0xffffffffu, s, 8);
    s += __shfl_xor_sync(0xffffffffu, s, 16);
    const float inv = 1.f / s;

    const int LS[4] = {0, 4096, 5120, 5376};
    const int WI[4] = {64, 32, 16, 8};

    float4 acc = make_float4(0.f, 0.f, 0.f, 0.f);
    #pragma unroll
    for (int l = 0; l < 4; ++l) {
        const int   Wi = WI[l], ls = LS[l];
        const float Wf = (float)Wi;
        const float2 o = *(const float2*)(off + (l * 4 + p4) * 2);
        const float x = fmaf(rx[l], Wf, o.x) - 0.5f;
        const float y = fmaf(ry[l], Wf, o.y) - 0.5f;
        const float xf = floorf(x), yf = floorf(y);
        const int x0 = (int)xf, y0 = (int)yf;
        const float fx = x - xf, fy = y - yf;
        const float vx0 = ((unsigned)x0       < (unsigned)Wi) ? 1.f : 0.f;
        const float vx1 = ((unsigned)(x0 + 1) < (unsigned)Wi) ? 1.f : 0.f;
        const float vy0 = ((unsigned)y0       < (unsigned)Wi) ? 1.f : 0.f;
        const float vy1 = ((unsigned)(y0 + 1) < (unsigned)Wi) ? 1.f : 0.f;
        const int x0c = min(max(x0, 0), Wi - 1), x1c = min(max(x0 + 1, 0), Wi - 1);
        const int y0c = min(max(y0, 0), Wi - 1), y1c = min(max(y0 + 1, 0), Wi - 1);

        const float wp  = e[l] * inv;
        const float wx0 = (1.f - fx) * vx0,      wx1 = fx * vx1;
        const float wy0 = (1.f - fy) * vy0 * wp, wy1 = fy * vy1 * wp;
        const float wa = wx0 * wy0, wb = wx0 * wy1, wc = wx1 * wy0, wd = wx1 * wy1;

        const __half* row0 = vb + (size_t)(ls + y0c * Wi) * EMBED;
        const __half* row1 = vb + (size_t)(ls + y1c * Wi) * EMBED;
        const int c0 = x0c * EMBED, c1 = x1c * EMBED;

        const uint2 u00 = *(const uint2*)(row0 + c0);
        const uint2 u01 = *(const uint2*)(row0 + c1);
        const uint2 u10 = *(const uint2*)(row1 + c0);
        const uint2 u11 = *(const uint2*)(row1 + c1);

        const float2 a00 = __half22float2(*(const __half2*)&u00.x);
        const float2 b00 = __half22float2(*(const __half2*)&u00.y);
        const float2 a01 = __half22float2(*(const __half2*)&u01.x);
        const float2 b01 = __half22float2(*(const __half2*)&u01.y);
        const float2 a10 = __half22float2(*(const __half2*)&u10.x);
        const float2 b10 = __half22float2(*(const __half2*)&u10.y);
        const float2 a11 = __half22float2(*(const __half2*)&u11.x);
        const float2 b11 = __half22float2(*(const __half2*)&u11.y);

        acc.x = fmaf(wa, a00.x, fmaf(wb, a10.x, fmaf(wc, a01.x, fmaf(wd, a11.x, acc.x))));
        acc.y = fmaf(wa, a00.y, fmaf(wb, a10.y, fmaf(wc, a01.y, fmaf(wd, a11.y, acc.y))));
        acc.z = fmaf(wa, b00.x, fmaf(wb, b10.x, fmaf(wc, b01.x, fmaf(wd, b11.x, acc.z))));
        acc.w = fmaf(wa, b00.y, fmaf(wb, b10.y, fmaf(wc, b01.y, fmaf(wd, b11.y, acc.w))));
    }

    acc.x += __shfl_xor_sync(0xffffffffu, acc.x, 8);
    acc.y += __shfl_xor_sync(0xffffffffu, acc.y, 8);
    acc.z += __shfl_xor_sync(0xffffffffu, acc.z, 8);
    acc.w += __shfl_xor_sync(0xffffffffu, acc.w, 8);
    acc.x += __shfl_xor_sync(0xffffffffu, acc.x, 16);
    acc.y += __shfl_xor_sync(0xffffffffu, acc.y, 16);
    acc.z += __shfl_xor_sync(0xffffffffu, acc.z, 16);
    acc.w += __shfl_xor_sync(0xffffffffu, acc.w, 16);

    if (p4 == 0) {
        union { __half2 h[2]; uint2 u; } U;
        U.h[0] = __floats2half2_rn(acc.x, acc.y);
        U.h[1] = __floats2half2_rn(acc.z, acc.w);
        const size_t vecidx = ((size_t)bq * EMBED + h * CDIM + cg * 4) / 4;
        ((uint2*)samp)[vecidx] = U.u;
    }
}

// ---------------- Launch ----------------
extern "C" void kernel_launch(void* const* d_in, const int* in_sizes, int n_in,
                              void* d_out, int out_size)
{
    const float* query   = (const float*)d_in[0];
    const float* ref_pts = (const float*)d_in[1];
    const float* value   = (const float*)d_in[2];
    const float* vproj_w = (const float*)d_in[5];
    const float* vproj_b = (const float*)d_in[6];
    const float* off_w   = (const float*)d_in[7];
    const float* off_b   = (const float*)d_in[8];
    const float* attn_w  = (const float*)d_in[9];
    const float* attn_b  = (const float*)d_in[10];
    const float* out_w   = (const float*)d_in[11];
    const float* out_b   = (const float*)d_in[12];
    float* out = (float*)d_out;

    __half *psamp, *pwh;
    cudaGetSymbolAddress((void**)&psamp, g_samp);
    cudaGetSymbolAddress((void**)&pwh,   g_wh);

    cudaFuncSetAttribute(gemm_proj, cudaFuncAttributeMaxDynamicSharedMemorySize, PROJ_SMEM);
    cudaFuncSetAttribute(gemm_out,  cudaFuncAttributeMaxDynamicSharedMemorySize, OUT_SMEM);

    // weight transpose
    conv_wt<<<dim3(256, 4), 256>>>(vproj_w, off_w, attn_w, out_w);

    // merged projections: v(fp16), off(fp32), awl(fp32) — fp32 A converted in-kernel
    gemm_proj<<<dim3(MROWS / 128, 10), 256, PROJ_SMEM>>>(
        value, query, pwh, vproj_b, off_b, attn_b);

    // sampling -> fp16 samp
    msda_sample<<<MROWS, 256>>>(ref_pts, psamp);

    // out-proj: out = samp @ out_w + b (fp32)
    gemm_out<<<dim3(MROWS / 128, 4), 256, OUT_SMEM>>>(
        psamp, pwh + 163840, out_b, out);
}

// round 14
// speedup vs baseline: 1.0158x; 1.0158x over previous
#include <cuda_runtime.h>
#include <cuda_bf16.h>
#include <cuda_fp16.h>
#include <cstdint>

// ---------------- Problem constants ----------------
#define EMBED   256
#define HEADS   8
#define LEVELS  4
#define POINTS  4
#define CDIM    32
#define LEN_V   5440
#define LEN_Q   5440
#define BSZ     4
#define MROWS   (BSZ * LEN_Q)   // 21760

// ---------------- Scratch ----------------
__device__ __half g_vh [(size_t)MROWS * EMBED];   // projected value, fp16
__device__ float  g_off[(size_t)MROWS * EMBED];
__device__ float  g_awl[(size_t)MROWS * 128];

__device__ __half g_af0[(size_t)MROWS * EMBED];   // value fp16, later samp fp16
__device__ __half g_af1[(size_t)MROWS * EMBED];   // query fp16

// fp16 transposed weights [N,K]: vproj:0, off:65536, attn:131072, out:163840
__device__ __half g_wh[229376];

// ---------------- PTX helpers (generic ISA only) ----------------
__device__ __forceinline__ uint32_t smem_u32(const void* p) {
    uint32_t a;
    asm("{ .reg .u64 t; cvta.to.shared.u64 t, %1; cvt.u32.u64 %0, t; }" : "=r"(a) : "l"(p));
    return a;
}
__device__ __forceinline__ void ldm_x4(uint32_t* r, uint32_t addr) {
    asm volatile("ldmatrix.sync.aligned.m8n8.x4.shared.b16 {%0,%1,%2,%3}, [%4];"
        : "=r"(r[0]), "=r"(r[1]), "=r"(r[2]), "=r"(r[3]) : "r"(addr));
}
__device__ __forceinline__ void mma_f16(float* c, const uint32_t* a, const uint32_t* b) {
    asm volatile(
        "mma.sync.aligned.m16n8k16.row.col.f32.f16.f16.f32 "
        "{%0,%1,%2,%3}, {%4,%5,%6,%7}, {%8,%9}, {%0,%1,%2,%3};"
        : "+f"(c[0]), "+f"(c[1]), "+f"(c[2]), "+f"(c[3])
        : "r"(a[0]), "r"(a[1]), "r"(a[2]), "r"(a[3]), "r"(b[0]), "r"(b[1]));
}
__device__ __forceinline__ void cp16(uint32_t dst, const void* src) {
    asm volatile("cp.async.cg.shared.global [%0], [%1], 16;" :: "r"(dst), "l"(src));
}
#define CP_COMMIT() asm volatile("cp.async.commit_group;" ::: "memory")

// swizzled smem offset (16-bit elements): row stride 64, 16B chunk xor (row&7)
__device__ __forceinline__ int swz(int row, int k) {
    return row * 64 + ((((k >> 3) ^ row) & 7) << 3) + (k & 7);
}

// ====================== single-pass fp16 GEMM ================================
// BM=128, BN=64, BK=64, 256 thr = 8 warps (4m x 2n), warp 32x32, 2-stage
// cp.async pipeline + register double-buffered fragments.
// MODE 0: fp32 C0 (N=256). MODE 1: fp16 C0 (N=256).
// MODE 2: dual fp32 (by<4 -> C0[256], else C1[128]).
#define F16_STAGE 24576
#define F16_SMEM  (2 * F16_STAGE)   // 48 KB

template<int MODE>
__global__ __launch_bounds__(256, 3)
void gemm_f16(const __half* __restrict__ A, const __half* __restrict__ BT,
              const float* __restrict__ bias0, const float* __restrict__ bias1,
              void* __restrict__ C0, void* __restrict__ C1)
{
    extern __shared__ char sm[];
    const uint32_t uS = smem_u32(sm);

    const int tid  = threadIdx.x;
    const int lane = tid & 31;
    const int wid  = tid >> 5;
    const int wm   = wid & 3;
    const int wn   = wid >> 2;
    const int bm   = blockIdx.x * 128;
    const int bn   = blockIdx.y * 64;

    const __half* pA = A  + (size_t)bm * EMBED;
    const __half* pB = BT + (size_t)bn * EMBED;

    const int grow = tid >> 3;
    const int gc8  = tid & 7;

    float c[2][4][4];
    #pragma unroll
    for (int mt = 0; mt < 2; ++mt)
        #pragma unroll
        for (int nt = 0; nt < 4; ++nt)
            #pragma unroll
            for (int i = 0; i < 4; ++i) c[mt][nt][i] = 0.f;

    auto stage_load = [&](int kc, int s) {
        const uint32_t sb = uS + s * F16_STAGE;
        #pragma unroll
        for (int t = 0; t < 4; ++t) {
            const int row = grow + t * 32;
            cp16(sb + (uint32_t)swz(row, gc8 * 8) * 2,
                 pA + (size_t)row * EMBED + kc * 64 + gc8 * 8);
        }
        #pragma unroll
        for (int t = 0; t < 2; ++t) {
            const int row = grow + t * 32;
            cp16(sb + 16384 + (uint32_t)swz(row, gc8 * 8) * 2,
                 pB + (size_t)row * EMBED + kc * 64 + gc8 * 8);
        }
        CP_COMMIT();
    };

    const int a_r = (lane & 15);
    const int a_k = (lane >> 4) << 3;
    const int b_n = ((lane >> 4) << 3) + (lane & 7);
    const int b_k = ((lane >> 3) & 1) << 3;

    // double-buffered fragments
    uint32_t af[2][2][4];   // [buf][mt][4]
    uint32_t bf[2][4][2];   // [buf][nt][2]

    auto frag_load = [&](uint32_t uA, uint32_t uB, int ks, int buf) {
        #pragma unroll
        for (int mt = 0; mt < 2; ++mt)
            ldm_x4(af[buf][mt], uA + swz(wm * 32 + mt * 16 + a_r, ks * 16 + a_k) * 2);
        #pragma unroll
        for (int np = 0; np < 2; ++np) {
            uint32_t t4[4];
            ldm_x4(t4, uB + swz(wn * 32 + np * 16 + b_n, ks * 16 + b_k) * 2);
            bf[buf][np * 2 + 0][0] = t4[0]; bf[buf][np * 2 + 0][1] = t4[1];
            bf[buf][np * 2 + 1][0] = t4[2]; bf[buf][np * 2 + 1][1] = t4[3];
        }
    };

    stage_load(0, 0);
    stage_load(1, 1);
    #pragma unroll
    for (int kc = 0; kc < 4; ++kc) {
        const int s = kc & 1;
        if (kc < 2) {
            asm volatile("cp.async.wait_group 1;" ::: "memory");
        } else {
            asm volatile("cp.async.wait_group 0;" ::: "memory");
        }
        __syncthreads();

        const uint32_t uA = uS + s * F16_STAGE;
        const uint32_t uB = uA + 16384;

        frag_load(uA, uB, 0, 0);
        #pragma unroll
        for (int ks = 0; ks < 4; ++ks) {
            if (ks < 3) frag_load(uA, uB, ks + 1, (ks + 1) & 1);
            const int buf = ks & 1;
            #pragma unroll
            for (int mt = 0; mt < 2; ++mt)
                #pragma unroll
                for (int nt = 0; nt < 4; ++nt)
                    mma_f16(c[mt][nt], af[buf][mt], bf[buf][nt]);
        }
        __syncthreads();
        if (kc < 2) stage_load(kc + 2, s);   // refill the stage just consumed
    }

    // ---- epilogue ----
    float* Cf = (float*)C0;
    const float* bs = bias0;
    int Nt = 256, colbase = bn;
    if (MODE == 2) {
        const bool isOff = (blockIdx.y < 4);
        Cf = isOff ? (float*)C0 : (float*)C1;
        bs = isOff ? bias0 : bias1;
        Nt = isOff ? 256 : 128;
        colbase = isOff ? bn : bn - 256;
    }
    #pragma unroll
    for (int mt = 0; mt < 2; ++mt) {
        const int r0 = bm + wm * 32 + mt * 16 + (lane >> 2);
        #pragma unroll
        for (int nt = 0; nt < 4; ++nt) {
            const int col = colbase + wn * 32 + nt * 8 + (lane & 3) * 2;
            const float2 bv = *(const float2*)(bs + col);
            const float o0x = c[mt][nt][0] + bv.x, o0y = c[mt][nt][1] + bv.y;
            const float o1x = c[mt][nt][2] + bv.x, o1y = c[mt][nt][3] + bv.y;
            if (MODE == 1) {
                __half* Ch = (__half*)C0;
                *(__half2*)(Ch + (size_t)r0 * 256 + col)       = __floats2half2_rn(o0x, o0y);
                *(__half2*)(Ch + (size_t)(r0 + 8) * 256 + col) = __floats2half2_rn(o1x, o1y);
            } else {
                *(float2*)(Cf + (size_t)r0 * Nt + col)       = make_float2(o0x, o0y);
                *(float2*)(Cf + (size_t)(r0 + 8) * Nt + col) = make_float2(o1x, o1y);
            }
        }
    }
}

// ---------------- conversions ----------------
__global__ __launch_bounds__(256)
void conv_act(const float* __restrict__ s0, const float* __restrict__ s1,
              __half* __restrict__ d0, __half* __restrict__ d1)
{
    const float* s = blockIdx.y ? s1 : s0;
    __half* d = blockIdx.y ? d1 : d0;
    const size_t i = (size_t)blockIdx.x * 256 + threadIdx.x;
    float4 x = ((const float4*)s)[i];
    union { __half2 h[2]; uint2 u; } U;
    U.h[0] = __floats2half2_rn(x.x, x.y);
    U.h[1] = __floats2half2_rn(x.z, x.w);
    ((uint2*)d)[i] = U.u;
}

// transpose: g_wh[off + n*256 + k] = W[k*N + n]
__global__ __launch_bounds__(256)
void conv_wt(const float* __restrict__ w0, const float* __restrict__ w1,
             const float* __restrict__ w2, const float* __restrict__ w3)
{
    const int m = blockIdx.y;
    const float* W = (m == 0) ? w0 : (m == 1) ? w1 : (m == 2) ? w2 : w3;
    const int N   = (m == 2) ? 128 : 256;
    const int off = (m == 0) ? 0 : (m == 1) ? 65536 : (m == 2) ? 131072 : 163840;
    const int idx = blockIdx.x * 256 + threadIdx.x;
    if (idx >= N * 256) return;
    const int k = idx & 255, n = idx >> 8;
    g_wh[off + idx] = __float2half(W[(size_t)k * N + n]);
}

// ---------------- Sampling kernel (fp16 v, fp16 samp output) ----------------
__global__ __launch_bounds__(256)
void msda_sample(const float* __restrict__ ref, __half* __restrict__ samp)
{
    const int bq   = blockIdx.x;
    const int b    = bq / LEN_Q;
    const int h    = threadIdx.x >> 5;
    const int lane = threadIdx.x & 31;
    const int p4   = lane >> 3;
    const int cg   = lane & 7;

    const float*  off = g_off + (size_t)bq * EMBED + h * 32;
    const float*  awl = g_awl + (size_t)bq * 128 + h * 16;
    const __half* vb  = g_vh + (size_t)b * LEN_V * EMBED + h * CDIM + cg * 4;
    const float*  rp  = ref + (size_t)bq * 8;

    float4 r01 = ((const float4*)rp)[0];
    float4 r23 = ((const float4*)rp)[1];
    const float rx[4] = {r01.x, r01.z, r23.x, r23.z};
    const float ry[4] = {r01.y, r01.w, r23.y, r23.w};

    float e[4];
    e[0] = awl[p4]; e[1] = awl[4 + p4]; e[2] = awl[8 + p4]; e[3] = awl[12 + p4];
    float mx = fmaxf(fmaxf(e[0], e[1]), fmaxf(e[2], e[3]));
    mx = fmaxf(mx, __shfl_xor_sync(0xffffffffu, mx, 8));
    mx = fmaxf(mx, __shfl_xor_sync(0xffffffffu, mx, 16));
    float s = 0.f;
    #pragma unroll
    for (int l = 0; l < 4; ++l) { e[l] = __expf(e[l] - mx); s += e[l]; }
    s += __shfl_xor_sync(0xffffffffu, s, 8);
    s += __shfl_xor_sync(0xffffffffu, s, 16);
    const float inv = 1.f / s;

    const int LS[4] = {0, 4096, 5120, 5376};
    const int WI[4] = {64, 32, 16, 8};

    float4 acc = make_float4(0.f, 0.f, 0.f, 0.f);
    #pragma unroll
    for (int l = 0; l < 4; ++l) {
        const int   Wi = WI[l], ls = LS[l];
        const float Wf = (float)Wi;
        const float2 o = *(const float2*)(off + (l * 4 + p4) * 2);
        const float x = fmaf(rx[l], Wf, o.x) - 0.5f;
        const float y = fmaf(ry[l], Wf, o.y) - 0.5f;
        const float xf = floorf(x), yf = floorf(y);
        const int x0 = (int)xf, y0 = (int)yf;
        const float fx = x - xf, fy = y - yf;
        const float vx0 = ((unsigned)x0       < (unsigned)Wi) ? 1.f : 0.f;
        const float vx1 = ((unsigned)(x0 + 1) < (unsigned)Wi) ? 1.f : 0.f;
        const float vy0 = ((unsigned)y0       < (unsigned)Wi) ? 1.f : 0.f;
        const float vy1 = ((unsigned)(y0 + 1) < (unsigned)Wi) ? 1.f : 0.f;
        const int x0c = min(max(x0, 0), Wi - 1), x1c = min(max(x0 + 1, 0), Wi - 1);
        const int y0c = min(max(y0, 0), Wi - 1), y1c = min(max(y0 + 1, 0), Wi - 1);

        const float wp  = e[l] * inv;
        const float wx0 = (1.f - fx) * vx0,      wx1 = fx * vx1;
        const float wy0 = (1.f - fy) * vy0 * wp, wy1 = fy * vy1 * wp;
        const float wa = wx0 * wy0, wb = wx0 * wy1, wc = wx1 * wy0, wd = wx1 * wy1;

        const __half* row0 = vb + (size_t)(ls + y0c * Wi) * EMBED;
        const __half* row1 = vb + (size_t)(ls + y1c * Wi) * EMBED;
        const int c0 = x0c * EMBED, c1 = x1c * EMBED;

        const uint2 u00 = *(const uint2*)(row0 + c0);
        const uint2 u01 = *(const uint2*)(row0 + c1);
        const uint2 u10 = *(const uint2*)(row1 + c0);
        const uint2 u11 = *(const uint2*)(row1 + c1);

        const float2 a00 = __half22float2(*(const __half2*)&u00.x);
        const float2 b00 = __half22float2(*(const __half2*)&u00.y);
        const float2 a01 = __half22float2(*(const __half2*)&u01.x);
        const float2 b01 = __half22float2(*(const __half2*)&u01.y);
        const float2 a10 = __half22float2(*(const __half2*)&u10.x);
        const float2 b10 = __half22float2(*(const __half2*)&u10.y);
        const float2 a11 = __half22float2(*(const __half2*)&u11.x);
        const float2 b11 = __half22float2(*(const __half2*)&u11.y);

        acc.x = fmaf(wa, a00.x, fmaf(wb, a10.x, fmaf(wc, a01.x, fmaf(wd, a11.x, acc.x))));
        acc.y = fmaf(wa, a00.y, fmaf(wb, a10.y, fmaf(wc, a01.y, fmaf(wd, a11.y, acc.y))));
        acc.z = fmaf(wa, b00.x, fmaf(wb, b10.x, fmaf(wc, b01.x, fmaf(wd, b11.x, acc.z))));
        acc.w = fmaf(wa, b00.y, fmaf(wb, b10.y, fmaf(wc, b01.y, fmaf(wd, b11.y, acc.w))));
    }

    acc.x += __shfl_xor_sync(0xffffffffu, acc.x, 8);
    acc.y += __shfl_xor_sync(0xffffffffu, acc.y, 8);
    acc.z += __shfl_xor_sync(0xffffffffu, acc.z, 8);
    acc.w += __shfl_xor_sync(0xffffffffu, acc.w, 8);
    acc.x += __shfl_xor_sync(0xffffffffu, acc.x, 16);
    acc.y += __shfl_xor_sync(0xffffffffu, acc.y, 16);
    acc.z += __shfl_xor_sync(0xffffffffu, acc.z, 16);
    acc.w += __shfl_xor_sync(0xffffffffu, acc.w, 16);

    if (p4 == 0) {
        union { __half2 h[2]; uint2 u; } U;
        U.h[0] = __floats2half2_rn(acc.x, acc.y);
        U.h[1] = __floats2half2_rn(acc.z, acc.w);
        const size_t vecidx = ((size_t)bq * EMBED + h * CDIM + cg * 4) / 4;
        ((uint2*)samp)[vecidx] = U.u;
    }
}

// ---------------- Launch ----------------
extern "C" void kernel_launch(void* const* d_in, const int* in_sizes, int n_in,
                              void* d_out, int out_size)
{
    const float* query   = (const float*)d_in[0];
    const float* ref_pts = (const float*)d_in[1];
    const float* value   = (const float*)d_in[2];
    const float* vproj_w = (const float*)d_in[5];
    const float* vproj_b = (const float*)d_in[6];
    const float* off_w   = (const float*)d_in[7];
    const float* off_b   = (const float*)d_in[8];
    const float* attn_w  = (const float*)d_in[9];
    const float* attn_b  = (const float*)d_in[10];
    const float* out_w   = (const float*)d_in[11];
    const float* out_b   = (const float*)d_in[12];
    float* out = (float*)d_out;

    __half *pvh, *paf0, *paf1, *pwh;
    float *poff, *pawl;
    cudaGetSymbolAddress((void**)&pvh,  g_vh);
    cudaGetSymbolAddress((void**)&poff, g_off);
    cudaGetSymbolAddress((void**)&pawl, g_awl);
    cudaGetSymbolAddress((void**)&paf0, g_af0);
    cudaGetSymbolAddress((void**)&paf1, g_af1);
    cudaGetSymbolAddress((void**)&pwh,  g_wh);

    cudaFuncSetAttribute(gemm_f16<0>, cudaFuncAttributeMaxDynamicSharedMemorySize, F16_SMEM);
    cudaFuncSetAttribute(gemm_f16<1>, cudaFuncAttributeMaxDynamicSharedMemorySize, F16_SMEM);
    cudaFuncSetAttribute(gemm_f16<2>, cudaFuncAttributeMaxDynamicSharedMemorySize, F16_SMEM);

    // weight transpose
    conv_wt<<<dim3(256, 4), 256>>>(vproj_w, off_w, attn_w, out_w);
    // activations fp32 -> fp16
    conv_act<<<dim3(MROWS * EMBED / 1024, 2), 256>>>(value, query, paf0, paf1);

    // GEMM1: v = value @ vproj_w + b  -> fp16
    gemm_f16<1><<<dim3(MROWS / 128, 4), 256, F16_SMEM>>>(
        paf0, pwh, vproj_b, nullptr, pvh, nullptr);
    // GEMM2+3 merged: [off | awl] = query @ [off_w | attn_w] + b
    gemm_f16<2><<<dim3(MROWS / 128, 6), 256, F16_SMEM>>>(
        paf1, pwh + 65536, off_b, attn_b, poff, pawl);

    // sampling (writes fp16 samp into g_af0, already consumed by GEMM1)
    msda_sample<<<MROWS, 256>>>(ref_pts, paf0);

    // out GEMM: out = samp @ out_w + b (fp32)
    gemm_f16<0><<<dim3(MROWS / 128, 4), 256, F16_SMEM>>>(
        paf0, pwh + 163840, out_b, nullptr, out, nullptr);
}

// round 15
// speedup vs baseline: 1.0592x; 1.0428x over previous
#include <cuda_runtime.h>
#include <cuda_bf16.h>
#include <cuda_fp16.h>
#include <cstdint>

// ---------------- Problem constants ----------------
#define EMBED   256
#define HEADS   8
#define LEVELS  4
#define POINTS  4
#define CDIM    32
#define LEN_V   5440
#define LEN_Q   5440
#define BSZ     4
#define MROWS   (BSZ * LEN_Q)   // 21760

// ---------------- Scratch ----------------
__device__ __half g_vh [(size_t)MROWS * EMBED];   // projected value, fp16
__device__ float  g_off[(size_t)MROWS * EMBED];
__device__ float  g_awl[(size_t)MROWS * 128];

__device__ __half g_af0[(size_t)MROWS * EMBED];   // value fp16, later samp fp16
__device__ __half g_af1[(size_t)MROWS * EMBED];   // query fp16

// fp16 transposed weights [N,K]: vproj:0, off:65536, attn:131072, out:163840
__device__ __half g_wh[229376];

// ---------------- PTX helpers (generic ISA only) ----------------
__device__ __forceinline__ uint32_t smem_u32(const void* p) {
    uint32_t a;
    asm("{ .reg .u64 t; cvta.to.shared.u64 t, %1; cvt.u32.u64 %0, t; }" : "=r"(a) : "l"(p));
    return a;
}
__device__ __forceinline__ void ldm_x4(uint32_t* r, uint32_t addr) {
    asm volatile("ldmatrix.sync.aligned.m8n8.x4.shared.b16 {%0,%1,%2,%3}, [%4];"
        : "=r"(r[0]), "=r"(r[1]), "=r"(r[2]), "=r"(r[3]) : "r"(addr));
}
__device__ __forceinline__ void mma_f16(float* c, const uint32_t* a, const uint32_t* b) {
    asm volatile(
        "mma.sync.aligned.m16n8k16.row.col.f32.f16.f16.f32 "
        "{%0,%1,%2,%3}, {%4,%5,%6,%7}, {%8,%9}, {%0,%1,%2,%3};"
        : "+f"(c[0]), "+f"(c[1]), "+f"(c[2]), "+f"(c[3])
        : "r"(a[0]), "r"(a[1]), "r"(a[2]), "r"(a[3]), "r"(b[0]), "r"(b[1]));
}
__device__ __forceinline__ void cp16(uint32_t dst, const void* src) {
    asm volatile("cp.async.cg.shared.global [%0], [%1], 16;" :: "r"(dst), "l"(src));
}
#define CP_COMMIT() asm volatile("cp.async.commit_group;" ::: "memory")

// swizzled smem offset (16-bit elements): row stride 64, 16B chunk xor (row&7)
__device__ __forceinline__ int swz(int row, int k) {
    return row * 64 + ((((k >> 3) ^ row) & 7) << 3) + (k & 7);
}

#define F16_STAGE 24576
#define F16_SMEM  (2 * F16_STAGE)   // 48 KB

// ====================== shared GEMM mainloop =================================
// BM=128, BN=64, BK=64, 256 thr = 8 warps (4m x 2n), warp 32x32, 2-stage
// cp.async pipeline + register double-buffered fragments.
struct GemmCtx {
    float c[2][4][4];
};

__device__ __forceinline__ void gemm_mainloop(
    GemmCtx& G, char* sm, uint32_t uS,
    const __half* __restrict__ pA, const __half* __restrict__ pB,
    int tid, int lane, int wm, int wn)
{
    const int grow = tid >> 3;
    const int gc8  = tid & 7;

    #pragma unroll
    for (int mt = 0; mt < 2; ++mt)
        #pragma unroll
        for (int nt = 0; nt < 4; ++nt)
            #pragma unroll
            for (int i = 0; i < 4; ++i) G.c[mt][nt][i] = 0.f;

    auto stage_load = [&](int kc, int s) {
        const uint32_t sb = uS + s * F16_STAGE;
        #pragma unroll
        for (int t = 0; t < 4; ++t) {
            const int row = grow + t * 32;
            cp16(sb + (uint32_t)swz(row, gc8 * 8) * 2,
                 pA + (size_t)row * EMBED + kc * 64 + gc8 * 8);
        }
        #pragma unroll
        for (int t = 0; t < 2; ++t) {
            const int row = grow + t * 32;
            cp16(sb + 16384 + (uint32_t)swz(row, gc8 * 8) * 2,
                 pB + (size_t)row * EMBED + kc * 64 + gc8 * 8);
        }
        CP_COMMIT();
    };

    const int a_r = (lane & 15);
    const int a_k = (lane >> 4) << 3;
    const int b_n = ((lane >> 4) << 3) + (lane & 7);
    const int b_k = ((lane >> 3) & 1) << 3;

    uint32_t af[2][2][4];
    uint32_t bf[2][4][2];

    auto frag_load = [&](uint32_t uA, uint32_t uB, int ks, int buf) {
        #pragma unroll
        for (int mt = 0; mt < 2; ++mt)
            ldm_x4(af[buf][mt], uA + swz(wm * 32 + mt * 16 + a_r, ks * 16 + a_k) * 2);
        #pragma unroll
        for (int np = 0; np < 2; ++np) {
            uint32_t t4[4];
            ldm_x4(t4, uB + swz(wn * 32 + np * 16 + b_n, ks * 16 + b_k) * 2);
            bf[buf][np * 2 + 0][0] = t4[0]; bf[buf][np * 2 + 0][1] = t4[1];
            bf[buf][np * 2 + 1][0] = t4[2]; bf[buf][np * 2 + 1][1] = t4[3];
        }
    };

    stage_load(0, 0);
    stage_load(1, 1);
    #pragma unroll
    for (int kc = 0; kc < 4; ++kc) {
        const int s = kc & 1;
        if (kc < 2) {
            asm volatile("cp.async.wait_group 1;" ::: "memory");
        } else {
            asm volatile("cp.async.wait_group 0;" ::: "memory");
        }
        __syncthreads();

        const uint32_t uA = uS + s * F16_STAGE;
        const uint32_t uB = uA + 16384;

        frag_load(uA, uB, 0, 0);
        #pragma unroll
        for (int ks = 0; ks < 4; ++ks) {
            if (ks < 3) frag_load(uA, uB, ks + 1, (ks + 1) & 1);
            const int buf = ks & 1;
            #pragma unroll
            for (int mt = 0; mt < 2; ++mt)
                #pragma unroll
                for (int nt = 0; nt < 4; ++nt)
                    mma_f16(G.c[mt][nt], af[buf][mt], bf[buf][nt]);
        }
        __syncthreads();
        if (kc < 2) stage_load(kc + 2, s);
    }
}

// ====================== merged projection GEMM ==============================
// grid (MROWS/128, 10): y<4 value->g_vh fp16; y in [4,8) query->g_off fp32;
// y in [8,10) query->g_awl fp32. Bitwise identical tiles vs separate launches.
__global__ __launch_bounds__(256, 3)
void gemm_proj(const __half* __restrict__ A0, const __half* __restrict__ A1,
               const __half* __restrict__ Wh,
               const float* __restrict__ bV, const float* __restrict__ bO,
               const float* __restrict__ bA)
{
    extern __shared__ char sm[];
    const uint32_t uS = smem_u32(sm);

    const int tid  = threadIdx.x;
    const int lane = tid & 31;
    const int wid  = tid >> 5;
    const int wm   = wid & 3;
    const int wn   = wid >> 2;
    const int bm   = blockIdx.x * 128;
    const int by   = blockIdx.y;

    const __half* pA = ((by < 4) ? A0 : A1) + (size_t)bm * EMBED;
    const __half* pB = (by < 4) ? (Wh + (size_t)by * 64 * 256)
                     : (by < 8) ? (Wh + 65536 + (size_t)(by - 4) * 64 * 256)
                                : (Wh + 131072 + (size_t)(by - 8) * 64 * 256);

    GemmCtx G;
    gemm_mainloop(G, sm, uS, pA, pB, tid, lane, wm, wn);

    if (by < 4) {
        const int colbase = by * 64;
        #pragma unroll
        for (int mt = 0; mt < 2; ++mt) {
            const int r0 = bm + wm * 32 + mt * 16 + (lane >> 2);
            #pragma unroll
            for (int nt = 0; nt < 4; ++nt) {
                const int col = colbase + wn * 32 + nt * 8 + (lane & 3) * 2;
                const float2 bv = *(const float2*)(bV + col);
                *(__half2*)(g_vh + (size_t)r0 * 256 + col) =
                    __floats2half2_rn(G.c[mt][nt][0] + bv.x, G.c[mt][nt][1] + bv.y);
                *(__half2*)(g_vh + (size_t)(r0 + 8) * 256 + col) =
                    __floats2half2_rn(G.c[mt][nt][2] + bv.x, G.c[mt][nt][3] + bv.y);
            }
        }
    } else {
        const bool isOff = (by < 8);
        float* Cf = isOff ? g_off : g_awl;
        const float* bs = isOff ? bO : bA;
        const int Nt = isOff ? 256 : 128;
        const int colbase = (isOff ? (by - 4) : (by - 8)) * 64;
        #pragma unroll
        for (int mt = 0; mt < 2; ++mt) {
            const int r0 = bm + wm * 32 + mt * 16 + (lane >> 2);
            #pragma unroll
            for (int nt = 0; nt < 4; ++nt) {
                const int col = colbase + wn * 32 + nt * 8 + (lane & 3) * 2;
                const float2 bv = *(const float2*)(bs + col);
                *(float2*)(Cf + (size_t)r0 * Nt + col) =
                    make_float2(G.c[mt][nt][0] + bv.x, G.c[mt][nt][1] + bv.y);
                *(float2*)(Cf + (size_t)(r0 + 8) * Nt + col) =
                    make_float2(G.c[mt][nt][2] + bv.x, G.c[mt][nt][3] + bv.y);
            }
        }
    }
}

// ====================== out-proj GEMM =======================================
__global__ __launch_bounds__(256, 3)
void gemm_out(const __half* __restrict__ A, const __half* __restrict__ BT,
              const float* __restrict__ bias, float* __restrict__ C)
{
    extern __shared__ char sm[];
    const uint32_t uS = smem_u32(sm);

    const int tid  = threadIdx.x;
    const int lane = tid & 31;
    const int wid  = tid >> 5;
    const int wm   = wid & 3;
    const int wn   = wid >> 2;
    const int bm   = blockIdx.x * 128;
    const int bn   = blockIdx.y * 64;

    GemmCtx G;
    gemm_mainloop(G, sm, uS, A + (size_t)bm * EMBED, BT + (size_t)bn * EMBED,
                  tid, lane, wm, wn);

    #pragma unroll
    for (int mt = 0; mt < 2; ++mt) {
        const int r0 = bm + wm * 32 + mt * 16 + (lane >> 2);
        #pragma unroll
        for (int nt = 0; nt < 4; ++nt) {
            const int col = bn + wn * 32 + nt * 8 + (lane & 3) * 2;
            const float2 bv = *(const float2*)(bias + col);
            *(float2*)(C + (size_t)r0 * 256 + col) =
                make_float2(G.c[mt][nt][0] + bv.x, G.c[mt][nt][1] + bv.y);
            *(float2*)(C + (size_t)(r0 + 8) * 256 + col) =
                make_float2(G.c[mt][nt][2] + bv.x, G.c[mt][nt][3] + bv.y);
        }
    }
}

// ---------------- fused conversions (acts + weight transpose) ----------------
// grid.x = 5440 (value) + 5440 (query) + 896 (weights) = 11776 blocks.
__global__ __launch_bounds__(256)
void conv_fuse(const float* __restrict__ value, const float* __restrict__ query,
               __half* __restrict__ d0, __half* __restrict__ d1,
               const float* __restrict__ w0, const float* __restrict__ w1,
               const float* __restrict__ w2, const float* __restrict__ w3)
{
    const int bx = blockIdx.x;
    if (bx < 10880) {
        const float* s = (bx < 5440) ? value : query;
        __half* d = (bx < 5440) ? d0 : d1;
        const size_t i = (size_t)(bx % 5440) * 256 + threadIdx.x;
        float4 x = ((const float4*)s)[i];
        union { __half2 h[2]; uint2 u; } U;
        U.h[0] = __floats2half2_rn(x.x, x.y);
        U.h[1] = __floats2half2_rn(x.z, x.w);
        ((uint2*)d)[i] = U.u;
    } else {
        const int gi = (bx - 10880) * 256 + threadIdx.x;   // [0, 229376)
        const float* W;
        int N, local;
        if (gi < 65536)       { W = w0; N = 256; local = gi; }
        else if (gi < 131072) { W = w1; N = 256; local = gi - 65536; }
        else if (gi < 163840) { W = w2; N = 128; local = gi - 131072; }
        else                  { W = w3; N = 256; local = gi - 163840; }
        const int k = local & 255, n = local >> 8;
        g_wh[gi] = __float2half(W[(size_t)k * N + n]);
    }
}

// ---------------- Sampling kernel (fp16 v, fp16 samp output) ----------------
__global__ __launch_bounds__(256)
void msda_sample(const float* __restrict__ ref, __half* __restrict__ samp)
{
    const int bq   = blockIdx.x;
    const int b    = bq / LEN_Q;
    const int h    = threadIdx.x >> 5;
    const int lane = threadIdx.x & 31;
    const int p4   = lane >> 3;
    const int cg   = lane & 7;

    const float*  off = g_off + (size_t)bq * EMBED + h * 32;
    const float*  awl = g_awl + (size_t)bq * 128 + h * 16;
    const __half* vb  = g_vh + (size_t)b * LEN_V * EMBED + h * CDIM + cg * 4;
    const float*  rp  = ref + (size_t)bq * 8;

    float4 r01 = ((const float4*)rp)[0];
    float4 r23 = ((const float4*)rp)[1];
    const float rx[4] = {r01.x, r01.z, r23.x, r23.z};
    const float ry[4] = {r01.y, r01.w, r23.y, r23.w};

    float e[4];
    e[0] = awl[p4]; e[1] = awl[4 + p4]; e[2] = awl[8 + p4]; e[3] = awl[12 + p4];
    float mx = fmaxf(fmaxf(e[0], e[1]), fmaxf(e[2], e[3]));
    mx = fmaxf(mx, __shfl_xor_sync(0xffffffffu, mx, 8));
    mx = fmaxf(mx, __shfl_xor_sync(0xffffffffu, mx, 16));
    float s = 0.f;
    #pragma unroll
    for (int l = 0; l < 4; ++l) { e[l] = __expf(e[l] - mx); s += e[l]; }
    s += __shfl_xor_sync(0xffffffffu, s, 8);
    s += __shfl_xor_sync(0xffffffffu, s, 16);
    const float inv = 1.f / s;

    const int LS[4] = {0, 4096, 5120, 5376};
    const int WI[4] = {64, 32, 16, 8};

    float4 acc = make_float4(0.f, 0.f, 0.f, 0.f);
    #pragma unroll
    for (int l = 0; l < 4; ++l) {
        const int   Wi = WI[l], ls = LS[l];
        const float Wf = (float)Wi;
        const float2 o = *(const float2*)(off + (l * 4 + p4) * 2);
        const float x = fmaf(rx[l], Wf, o.x) - 0.5f;
        const float y = fmaf(ry[l], Wf, o.y) - 0.5f;
        const float xf = floorf(x), yf = floorf(y);
        const int x0 = (int)xf, y0 = (int)yf;
        const float fx = x - xf, fy = y - yf;
        const float vx0 = ((unsigned)x0       < (unsigned)Wi) ? 1.f : 0.f;
        const float vx1 = ((unsigned)(x0 + 1) < (unsigned)Wi) ? 1.f : 0.f;
        const float vy0 = ((unsigned)y0       < (unsigned)Wi) ? 1.f : 0.f;
        const float vy1 = ((unsigned)(y0 + 1) < (unsigned)Wi) ? 1.f : 0.f;
        const int x0c = min(max(x0, 0), Wi - 1), x1c = min(max(x0 + 1, 0), Wi - 1);
        const int y0c = min(max(y0, 0), Wi - 1), y1c = min(max(y0 + 1, 0), Wi - 1);

        const float wp  = e[l] * inv;
        const float wx0 = (1.f - fx) * vx0,      wx1 = fx * vx1;
        const float wy0 = (1.f - fy) * vy0 * wp, wy1 = fy * vy1 * wp;
        const float wa = wx0 * wy0, wb = wx0 * wy1, wc = wx1 * wy0, wd = wx1 * wy1;

        const __half* row0 = vb + (size_t)(ls + y0c * Wi) * EMBED;
        const __half* row1 = vb + (size_t)(ls + y1c * Wi) * EMBED;
        const int c0 = x0c * EMBED, c1 = x1c * EMBED;

        const uint2 u00 = *(const uint2*)(row0 + c0);
        const uint2 u01 = *(const uint2*)(row0 + c1);
        const uint2 u10 = *(const uint2*)(row1 + c0);
        const uint2 u11 = *(const uint2*)(row1 + c1);

        const float2 a00 = __half22float2(*(const __half2*)&u00.x);
        const float2 b00 = __half22float2(*(const __half2*)&u00.y);
        const float2 a01 = __half22float2(*(const __half2*)&u01.x);
        const float2 b01 = __half22float2(*(const __half2*)&u01.y);
        const float2 a10 = __half22float2(*(const __half2*)&u10.x);
        const float2 b10 = __half22float2(*(const __half2*)&u10.y);
        const float2 a11 = __half22float2(*(const __half2*)&u11.x);
        const float2 b11 = __half22float2(*(const __half2*)&u11.y);

        acc.x = fmaf(wa, a00.x, fmaf(wb, a10.x, fmaf(wc, a01.x, fmaf(wd, a11.x, acc.x))));
        acc.y = fmaf(wa, a00.y, fmaf(wb, a10.y, fmaf(wc, a01.y, fmaf(wd, a11.y, acc.y))));
        acc.z = fmaf(wa, b00.x, fmaf(wb, b10.x, fmaf(wc, b01.x, fmaf(wd, b11.x, acc.z))));
        acc.w = fmaf(wa, b00.y, fmaf(wb, b10.y, fmaf(wc, b01.y, fmaf(wd, b11.y, acc.w))));
    }

    acc.x += __shfl_xor_sync(0xffffffffu, acc.x, 8);
    acc.y += __shfl_xor_sync(0xffffffffu, acc.y, 8);
    acc.z += __shfl_xor_sync(0xffffffffu, acc.z, 8);
    acc.w += __shfl_xor_sync(0xffffffffu, acc.w, 8);
    acc.x += __shfl_xor_sync(0xffffffffu, acc.x, 16);
    acc.y += __shfl_xor_sync(0xffffffffu, acc.y, 16);
    acc.z += __shfl_xor_sync(0xffffffffu, acc.z, 16);
    acc.w += __shfl_xor_sync(0xffffffffu, acc.w, 16);

    if (p4 == 0) {
        union { __half2 h[2]; uint2 u; } U;
        U.h[0] = __floats2half2_rn(acc.x, acc.y);
        U.h[1] = __floats2half2_rn(acc.z, acc.w);
        const size_t vecidx = ((size_t)bq * EMBED + h * CDIM + cg * 4) / 4;
        ((uint2*)samp)[vecidx] = U.u;
    }
}

// ---------------- Launch ----------------
extern "C" void kernel_launch(void* const* d_in, const int* in_sizes, int n_in,
                              void* d_out, int out_size)
{
    const float* query   = (const float*)d_in[0];
    const float* ref_pts = (const float*)d_in[1];
    const float* value   = (const float*)d_in[2];
    const float* vproj_w = (const float*)d_in[5];
    const float* vproj_b = (const float*)d_in[6];
    const float* off_w   = (const float*)d_in[7];
    const float* off_b   = (const float*)d_in[8];
    const float* attn_w  = (const float*)d_in[9];
    const float* attn_b  = (const float*)d_in[10];
    const float* out_w   = (const float*)d_in[11];
    const float* out_b   = (const float*)d_in[12];
    float* out = (float*)d_out;

    __half *paf0, *paf1, *pwh;
    cudaGetSymbolAddress((void**)&paf0, g_af0);
    cudaGetSymbolAddress((void**)&paf1, g_af1);
    cudaGetSymbolAddress((void**)&pwh,  g_wh);

    cudaFuncSetAttribute(gemm_proj, cudaFuncAttributeMaxDynamicSharedMemorySize, F16_SMEM);
    cudaFuncSetAttribute(gemm_out,  cudaFuncAttributeMaxDynamicSharedMemorySize, F16_SMEM);

    // fused: activations fp32->fp16 + weight transpose
    conv_fuse<<<11776, 256>>>(value, query, paf0, paf1,
                              vproj_w, off_w, attn_w, out_w);

    // merged projections: v(fp16), off(fp32), awl(fp32)
    gemm_proj<<<dim3(MROWS / 128, 10), 256, F16_SMEM>>>(
        paf0, paf1, pwh, vproj_b, off_b, attn_b);

    // sampling (writes fp16 samp into g_af0, already consumed by gemm_proj)
    msda_sample<<<MROWS, 256>>>(ref_pts, paf0);

    // out GEMM: out = samp @ out_w + b (fp32)
    gemm_out<<<dim3(MROWS / 128, 4), 256, F16_SMEM>>>(
        paf0, pwh + 163840, out_b, out);
}